// round 1
// baseline (speedup 1.0000x reference)
#include <cuda_runtime.h>
#include <cuda_bf16.h>

// out[c, n] = sum over (h, k) with octree[h,k]==n of data_in[c, k, h]
// data_in: [C, K, H] float32 ; octree: [H, K] int32 ; out: [C, N] float32, N==H

__global__ void zero_out_kernel(float4* __restrict__ out, int n4) {
    int i = blockIdx.x * blockDim.x + threadIdx.x;
    if (i < n4) out[i] = make_float4(0.f, 0.f, 0.f, 0.f);
}

__global__ void col2octree_scatter_kernel(
    const float* __restrict__ data_in,   // [C, K, N]
    const int*   __restrict__ octree,    // [N(=H), K]
    float*       __restrict__ out,       // [C, N]
    int C, int K, int N)
{
    const int h = blockIdx.x * blockDim.x + threadIdx.x;
    const int k = blockIdx.y;
    if (h >= N) return;

    const int idx = __ldg(&octree[h * K + k]);
    if (idx < 0) return;

    // data_in[c, k, h] = data_in[(c*K + k)*N + h]; consecutive lanes -> consecutive h
    const float* src = data_in + (size_t)k * N + h;
    float* dst = out + idx;
    const size_t src_stride = (size_t)K * N;  // per-channel stride in data_in
    const size_t dst_stride = (size_t)N;      // per-channel stride in out

    #pragma unroll 8
    for (int c = 0; c < C; ++c) {
        float v = __ldg(src + (size_t)c * src_stride);
        atomicAdd(dst + (size_t)c * dst_stride, v);  // unused return -> RED.E.ADD.F32
    }
}

extern "C" void kernel_launch(void* const* d_in, const int* in_sizes, int n_in,
                              void* d_out, int out_size) {
    const float* data_in = (const float*)d_in[0];
    const int*   octree  = (const int*)d_in[1];
    float*       out     = (float*)d_out;

    // in_sizes[0] = C*K*N, in_sizes[1] = N*K, out_size = C*N
    const long long in0 = in_sizes[0];
    const long long in1 = in_sizes[1];
    const int C = (int)(in0 / in1);          // 64
    const int K = (int)(in0 / out_size);     // 27
    const int N = (int)(out_size / C);       // 200000

    // Zero the output (poisoned by harness).
    {
        int n4 = out_size / 4;
        int threads = 256;
        int blocks = (n4 + threads - 1) / threads;
        zero_out_kernel<<<blocks, threads>>>((float4*)out, n4);
    }

    // Scatter-add.
    {
        dim3 threads(256, 1, 1);
        dim3 blocks((N + 255) / 256, K, 1);
        col2octree_scatter_kernel<<<blocks, threads>>>(data_in, octree, out, C, K, N);
    }
}

// round 2
// speedup vs baseline: 2.6449x; 2.6449x over previous
#include <cuda_runtime.h>
#include <cuda_bf16.h>

// out[c, n] = sum over (h, k) with octree[h,k]==n of data_in[c, k, h]
// data_in: [C, K, H] f32 ; octree: [H, K] i32 ; out: [C, N] f32, N==H.
// Strategy: scatter with red.global.add.v4.f32 into [N, C] scratch
// (channels contiguous -> 16B vector atomics), then transpose to [C, N].

#define MAX_N 200000
#define CH    64

__device__ float g_scratch[(size_t)MAX_N * CH];   // 51.2 MB, [N, C] layout

__global__ void zero_scratch_kernel(float4* __restrict__ p, int n4) {
    int i = blockIdx.x * blockDim.x + threadIdx.x;
    if (i < n4) p[i] = make_float4(0.f, 0.f, 0.f, 0.f);
}

__global__ void col2octree_scatter_v4(
    const float* __restrict__ data_in,   // [C, K, N]
    const int*   __restrict__ octree,    // [N(=H), K]
    int C, int K, int N)
{
    const int h = blockIdx.x * blockDim.x + threadIdx.x;
    const int k = blockIdx.y;
    if (h >= N) return;

    const int idx = __ldg(&octree[h * K + k]);
    if (idx < 0) return;

    // data_in[c, k, h] = data_in[(c*K + k)*N + h]; lanes contiguous along h.
    const float* src = data_in + (size_t)k * N + h;
    const size_t cs = (size_t)K * N;             // per-channel stride
    float* dst = g_scratch + (size_t)idx * CH;   // [N, C]: channels contiguous

    #pragma unroll 4
    for (int c = 0; c < CH; c += 4) {
        // streaming loads (evict-first): keep L2 capacity for the scratch
        float a = __ldcs(src + (size_t)(c + 0) * cs);
        float b = __ldcs(src + (size_t)(c + 1) * cs);
        float d = __ldcs(src + (size_t)(c + 2) * cs);
        float e = __ldcs(src + (size_t)(c + 3) * cs);
        asm volatile("red.global.add.v4.f32 [%0], {%1, %2, %3, %4};"
                     :: "l"(dst + c), "f"(a), "f"(b), "f"(d), "f"(e)
                     : "memory");
    }
}

// [N, C] -> [C, N] transpose, 32x32 tiles via shared memory.
__global__ void transpose_nc_to_cn(
    const float* __restrict__ scratch,   // [N, C]
    float*       __restrict__ out,       // [C, N]
    int C, int N)
{
    __shared__ float tile[32][33];
    const int n0 = blockIdx.x * 32;
    const int c0 = blockIdx.y * 32;
    const int tx = threadIdx.x;          // 0..31
    const int ty = threadIdx.y;          // 0..7

    #pragma unroll
    for (int i = ty; i < 32; i += 8) {
        int n = n0 + i;
        int c = c0 + tx;
        tile[i][tx] = (n < N && c < C) ? scratch[(size_t)n * C + c] : 0.f;
    }
    __syncthreads();
    #pragma unroll
    for (int i = ty; i < 32; i += 8) {
        int c = c0 + i;
        int n = n0 + tx;
        if (n < N && c < C) out[(size_t)c * N + n] = tile[tx][i];
    }
}

extern "C" void kernel_launch(void* const* d_in, const int* in_sizes, int n_in,
                              void* d_out, int out_size) {
    const float* data_in = (const float*)d_in[0];
    const int*   octree  = (const int*)d_in[1];
    float*       out     = (float*)d_out;

    const long long in0 = in_sizes[0];          // C*K*N
    const long long in1 = in_sizes[1];          // N*K
    const int C = (int)(in0 / in1);             // 64
    const int K = (int)(in0 / out_size);        // 27
    const int N = (int)(out_size / C);          // 200000

    float* scratch_ptr = nullptr;
    cudaGetSymbolAddress((void**)&scratch_ptr, g_scratch);

    // 1) zero the [N, C] scratch
    {
        int n4 = (N * C) / 4;
        int threads = 256;
        int blocks = (n4 + threads - 1) / threads;
        zero_scratch_kernel<<<blocks, threads>>>((float4*)scratch_ptr, n4);
    }

    // 2) scatter-add with v4 vector atomics into [N, C] scratch
    {
        dim3 threads(256, 1, 1);
        dim3 blocks((N + 255) / 256, K, 1);
        col2octree_scatter_v4<<<blocks, threads>>>(data_in, octree, C, K, N);
    }

    // 3) transpose [N, C] -> [C, N]
    {
        dim3 threads(32, 8, 1);
        dim3 blocks((N + 31) / 32, (C + 31) / 32, 1);
        transpose_nc_to_cn<<<blocks, threads>>>(scratch_ptr, out, C, N);
    }
}

// round 3
// speedup vs baseline: 2.7949x; 1.0567x over previous
#include <cuda_runtime.h>
#include <cuda_bf16.h>

// out[c, n] = sum over (h, k) with octree[h,k]==n of data_in[c, k, h]
// data_in: [C, K, H] f32 ; octree: [H, K] i32 ; out: [C, N] f32, N==H.
// v4 vector atomics into [N, C] scratch, coalesced index loads via
// pre-transposed octree, then transpose scratch -> [C, N].

#define MAX_N 200000
#define CH    64
#define KK    27

__device__ float g_scratch[(size_t)MAX_N * CH];      // 51.2 MB, [N, C]
__device__ int   g_octree_t[(size_t)KK * MAX_N];     // 21.6 MB, [K, N]

__global__ void zero_scratch_kernel(float4* __restrict__ p, int n4) {
    int i = blockIdx.x * blockDim.x + threadIdx.x;
    if (i < n4) p[i] = make_float4(0.f, 0.f, 0.f, 0.f);
}

// octree [N, K] -> octree_t [K, N]; 32 n-rows per block via smem tile.
__global__ void transpose_octree(const int* __restrict__ oct, int* __restrict__ oct_t,
                                 int K, int N) {
    __shared__ int tile[32 * KK];
    const int n0 = blockIdx.x * 32;
    const int tid = threadIdx.x;              // 256 threads
    const int total = 32 * K;
    // coalesced read of rows [n0, n0+32)
    for (int i = tid; i < total; i += 256) {
        int n = n0 + i / K;
        tile[i] = (n < N) ? oct[(size_t)n0 * K + i] : -1;
    }
    __syncthreads();
    // coalesced write: 8 k's per pass, 32 n's wide
    const int r = tid & 31;
    const int kq = tid >> 5;                  // 0..7
    for (int k = kq; k < K; k += 8) {
        int n = n0 + r;
        if (n < N) oct_t[(size_t)k * N + n] = tile[r * K + k];
    }
}

__global__ void col2octree_scatter_v4(
    const float* __restrict__ data_in,   // [C, K, N]
    const int*   __restrict__ oct_t,     // [K, N]
    int C, int K, int N)
{
    const int h = blockIdx.x * blockDim.x + threadIdx.x;
    const int k = blockIdx.y;
    if (h >= N) return;

    const int idx = __ldg(&oct_t[(size_t)k * N + h]);   // coalesced
    if (idx < 0) return;

    const float* src = data_in + (size_t)k * N + h;      // lanes contiguous along h
    const size_t cs = (size_t)K * N;                     // per-channel stride
    float* dst = g_scratch + (size_t)idx * CH;           // [N, C]: 16B-aligned groups

    #pragma unroll
    for (int c0 = 0; c0 < CH; c0 += 16) {
        float v[16];
        #pragma unroll
        for (int j = 0; j < 16; ++j)
            v[j] = __ldcs(src + (size_t)(c0 + j) * cs);  // 16 loads in flight
        #pragma unroll
        for (int j = 0; j < 16; j += 4) {
            asm volatile("red.global.add.v4.f32 [%0], {%1, %2, %3, %4};"
                         :: "l"(dst + c0 + j),
                            "f"(v[j]), "f"(v[j+1]), "f"(v[j+2]), "f"(v[j+3])
                         : "memory");
        }
    }
}

// [N, C] -> [C, N] transpose, 32x32 tiles via shared memory.
__global__ void transpose_nc_to_cn(
    const float* __restrict__ scratch,   // [N, C]
    float*       __restrict__ out,       // [C, N]
    int C, int N)
{
    __shared__ float tile[32][33];
    const int n0 = blockIdx.x * 32;
    const int c0 = blockIdx.y * 32;
    const int tx = threadIdx.x;
    const int ty = threadIdx.y;

    #pragma unroll
    for (int i = ty; i < 32; i += 8) {
        int n = n0 + i;
        int c = c0 + tx;
        tile[i][tx] = (n < N && c < C) ? scratch[(size_t)n * C + c] : 0.f;
    }
    __syncthreads();
    #pragma unroll
    for (int i = ty; i < 32; i += 8) {
        int c = c0 + i;
        int n = n0 + tx;
        if (n < N && c < C) out[(size_t)c * N + n] = tile[tx][i];
    }
}

extern "C" void kernel_launch(void* const* d_in, const int* in_sizes, int n_in,
                              void* d_out, int out_size) {
    const float* data_in = (const float*)d_in[0];
    const int*   octree  = (const int*)d_in[1];
    float*       out     = (float*)d_out;

    const long long in0 = in_sizes[0];          // C*K*N
    const long long in1 = in_sizes[1];          // N*K
    const int C = (int)(in0 / in1);             // 64
    const int K = (int)(in0 / out_size);        // 27
    const int N = (int)(out_size / C);          // 200000

    float* scratch_ptr = nullptr;
    int*   oct_t_ptr   = nullptr;
    cudaGetSymbolAddress((void**)&scratch_ptr, g_scratch);
    cudaGetSymbolAddress((void**)&oct_t_ptr, g_octree_t);

    // 1) zero the [N, C] scratch
    {
        int n4 = (N * C) / 4;
        zero_scratch_kernel<<<(n4 + 255) / 256, 256>>>((float4*)scratch_ptr, n4);
    }
    // 2) transpose octree [N, K] -> [K, N]
    {
        transpose_octree<<<(N + 31) / 32, 256>>>(octree, oct_t_ptr, K, N);
    }
    // 3) scatter-add with v4 vector atomics into [N, C] scratch
    {
        dim3 threads(256, 1, 1);
        dim3 blocks((N + 255) / 256, K, 1);
        col2octree_scatter_v4<<<blocks, threads>>>(data_in, oct_t_ptr, C, K, N);
    }
    // 4) transpose [N, C] -> [C, N]
    {
        dim3 threads(32, 8, 1);
        dim3 blocks((N + 31) / 32, (C + 31) / 32, 1);
        transpose_nc_to_cn<<<blocks, threads>>>(scratch_ptr, out, C, N);
    }
}

// round 4
// speedup vs baseline: 2.8043x; 1.0034x over previous
#include <cuda_runtime.h>
#include <cuda_bf16.h>
#include <cstdint>

// out[c, n] = sum over (h, k) with octree[h,k]==n of data_in[c, k, h]
// data_in: [C, K, H] f32 ; octree: [H, K] i32 ; out: [C, N] f32, N==H.
// Scatter via 256B TMA bulk-reduce (cp.reduce.async.bulk) into [N, C] scratch
// (full-sector RMW payload), then transpose scratch -> [C, N].

#define MAX_N 200000
#define CH    64
#define KK    27
#define TILE_H 32
#define SMEM_STRIDE 68   // floats; 272B = 16B-aligned column base, 4-way STS conflict

__device__ float g_scratch[(size_t)MAX_N * CH];      // 51.2 MB, [N, C]
__device__ int   g_octree_t[(size_t)KK * MAX_N];     // 21.6 MB, [K, N]

__device__ __forceinline__ uint32_t smem_u32(const void* p) {
    uint32_t a;
    asm("{ .reg .u64 t; cvta.to.shared.u64 t, %1; cvt.u32.u64 %0, t; }"
        : "=r"(a) : "l"(p));
    return a;
}

__global__ void zero_scratch_kernel(float4* __restrict__ p, int n4) {
    int i = blockIdx.x * blockDim.x + threadIdx.x;
    if (i < n4) p[i] = make_float4(0.f, 0.f, 0.f, 0.f);
}

// octree [N, K] -> octree_t [K, N]
__global__ void transpose_octree(const int* __restrict__ oct, int* __restrict__ oct_t,
                                 int K, int N) {
    __shared__ int tile[32 * KK];
    const int n0 = blockIdx.x * 32;
    const int tid = threadIdx.x;              // 256
    const int total = 32 * K;
    for (int i = tid; i < total; i += 256) {
        int n = n0 + i / K;
        tile[i] = (n < N) ? oct[(size_t)n0 * K + i] : -1;
    }
    __syncthreads();
    const int r = tid & 31;
    const int kq = tid >> 5;
    for (int k = kq; k < K; k += 8) {
        int n = n0 + r;
        if (n < N) oct_t[(size_t)k * N + n] = tile[r * K + k];
    }
}

// One block: 32 h's of one k. Load 64c x 32h coalesced, transpose in smem,
// warp 0 issues one 256B bulk-reduce per h into scratch[idx*64].
__global__ void col2octree_scatter_tma(
    const float* __restrict__ data_in,   // [C, K, N]
    const int*   __restrict__ oct_t,     // [K, N]
    float*       __restrict__ scratch,   // [N, C]
    int K, int N)
{
    __shared__ __align__(16) float tile[TILE_H * SMEM_STRIDE];

    const int k    = blockIdx.y;
    const int h0   = blockIdx.x * TILE_H;
    const int t    = threadIdx.x;        // 256 threads
    const int lane = t & 31;
    const int w    = t >> 5;             // 8 warps
    const int hmax = N - h0;             // full tiles when N % 32 == 0

    const float* src = data_in + (size_t)k * N + h0;
    const size_t cs = (size_t)K * N;

    #pragma unroll
    for (int c = w; c < CH; c += 8) {
        float v = 0.f;
        if (lane < hmax) v = __ldcs(src + (size_t)c * cs + lane);
        tile[lane * SMEM_STRIDE + c] = v;
    }
    __syncthreads();

    if (w == 0) {
        if (lane < TILE_H && lane < hmax) {
            const int idx = __ldg(&oct_t[(size_t)k * N + h0 + lane]);
            if (idx >= 0) {
                uint32_t s = smem_u32(&tile[lane * SMEM_STRIDE]);
                float* d = scratch + (size_t)idx * CH;
                asm volatile(
                    "cp.reduce.async.bulk.global.shared::cta.bulk_group.add.f32 "
                    "[%0], [%1], %2;"
                    :: "l"(d), "r"(s), "r"((uint32_t)(CH * 4))
                    : "memory");
            }
        }
        asm volatile("cp.async.bulk.commit_group;" ::: "memory");
        asm volatile("cp.async.bulk.wait_group 0;" ::: "memory");
    }
}

// Fallback scalar-v4 scatter (used only if C != 64)
__global__ void col2octree_scatter_v4(
    const float* __restrict__ data_in, const int* __restrict__ oct_t,
    float* __restrict__ scratch, int C, int K, int N)
{
    const int h = blockIdx.x * blockDim.x + threadIdx.x;
    const int k = blockIdx.y;
    if (h >= N) return;
    const int idx = __ldg(&oct_t[(size_t)k * N + h]);
    if (idx < 0) return;
    const float* src = data_in + (size_t)k * N + h;
    const size_t cs = (size_t)K * N;
    float* dst = scratch + (size_t)idx * C;
    for (int c = 0; c + 4 <= C; c += 4) {
        float a = __ldcs(src + (size_t)(c + 0) * cs);
        float b = __ldcs(src + (size_t)(c + 1) * cs);
        float d = __ldcs(src + (size_t)(c + 2) * cs);
        float e = __ldcs(src + (size_t)(c + 3) * cs);
        asm volatile("red.global.add.v4.f32 [%0], {%1, %2, %3, %4};"
                     :: "l"(dst + c), "f"(a), "f"(b), "f"(d), "f"(e) : "memory");
    }
}

// [N, C] -> [C, N] transpose, 32x32 tiles via shared memory.
__global__ void transpose_nc_to_cn(
    const float* __restrict__ scratch, float* __restrict__ out, int C, int N)
{
    __shared__ float tile[32][33];
    const int n0 = blockIdx.x * 32;
    const int c0 = blockIdx.y * 32;
    const int tx = threadIdx.x;
    const int ty = threadIdx.y;

    #pragma unroll
    for (int i = ty; i < 32; i += 8) {
        int n = n0 + i;
        int c = c0 + tx;
        tile[i][tx] = (n < N && c < C) ? scratch[(size_t)n * C + c] : 0.f;
    }
    __syncthreads();
    #pragma unroll
    for (int i = ty; i < 32; i += 8) {
        int c = c0 + i;
        int n = n0 + tx;
        if (n < N && c < C) out[(size_t)c * N + n] = tile[tx][i];
    }
}

extern "C" void kernel_launch(void* const* d_in, const int* in_sizes, int n_in,
                              void* d_out, int out_size) {
    const float* data_in = (const float*)d_in[0];
    const int*   octree  = (const int*)d_in[1];
    float*       out     = (float*)d_out;

    const long long in0 = in_sizes[0];          // C*K*N
    const long long in1 = in_sizes[1];          // N*K
    const int C = (int)(in0 / in1);             // 64
    const int K = (int)(in0 / out_size);        // 27
    const int N = (int)(out_size / C);          // 200000

    float* scratch_ptr = nullptr;
    int*   oct_t_ptr   = nullptr;
    cudaGetSymbolAddress((void**)&scratch_ptr, g_scratch);
    cudaGetSymbolAddress((void**)&oct_t_ptr, g_octree_t);

    // 1) zero the [N, C] scratch
    {
        int n4 = (N * C) / 4;
        zero_scratch_kernel<<<(n4 + 255) / 256, 256>>>((float4*)scratch_ptr, n4);
    }
    // 2) transpose octree [N, K] -> [K, N]
    transpose_octree<<<(N + 31) / 32, 256>>>(octree, oct_t_ptr, K, N);

    // 3) scatter-add
    if (C == CH) {
        dim3 blocks((N + TILE_H - 1) / TILE_H, K, 1);
        col2octree_scatter_tma<<<blocks, 256>>>(data_in, oct_t_ptr, scratch_ptr, K, N);
    } else {
        dim3 blocks((N + 255) / 256, K, 1);
        col2octree_scatter_v4<<<blocks, 256>>>(data_in, oct_t_ptr, scratch_ptr, C, K, N);
    }
    // 4) transpose [N, C] -> [C, N]
    {
        dim3 threads(32, 8, 1);
        dim3 blocks((N + 31) / 32, (C + 31) / 32, 1);
        transpose_nc_to_cn<<<blocks, threads>>>(scratch_ptr, out, C, N);
    }
}

// round 5
// speedup vs baseline: 4.5883x; 1.6361x over previous
#include <cuda_runtime.h>
#include <cuda_bf16.h>
#include <cstdint>

// out[c, n] = sum over (h, k) with octree[h,k]==n of data_in[c, k, h]
// data_in: [C, K, H] f32 ; octree: [H, K] i32 ; out: [C, N] f32, N==H.
// Scatter via per-thread 256B TMA bulk-reduce into [N, C] scratch, with
// parallel issue from 128 threads/block; then transpose scratch -> [C, N].

#define MAX_N 200000
#define CH    64
#define KK    27
#define TILE_H 128
#define SSTR  68   // smem row stride in floats: 272B (16B-aligned, float4-STS conflict-free)

__device__ float g_scratch[(size_t)MAX_N * CH];      // 51.2 MB, [N, C]
__device__ int   g_octree_t[(size_t)KK * MAX_N];     // 21.6 MB, [K, N]

__device__ __forceinline__ uint32_t smem_u32(const void* p) {
    uint32_t a;
    asm("{ .reg .u64 t; cvta.to.shared.u64 t, %1; cvt.u32.u64 %0, t; }"
        : "=r"(a) : "l"(p));
    return a;
}

// octree [N, K] -> octree_t [K, N]
__global__ void transpose_octree(const int* __restrict__ oct, int* __restrict__ oct_t,
                                 int K, int N) {
    __shared__ int tile[32 * KK];
    const int n0 = blockIdx.x * 32;
    const int tid = threadIdx.x;              // 256
    const int total = 32 * K;
    for (int i = tid; i < total; i += 256) {
        int n = n0 + i / K;
        tile[i] = (n < N) ? oct[(size_t)n0 * K + i] : -1;
    }
    __syncthreads();
    const int r = tid & 31;
    const int kq = tid >> 5;
    for (int k = kq; k < K; k += 8) {
        int n = n0 + r;
        if (n < N) oct_t[(size_t)k * N + n] = tile[r * K + k];
    }
}

// Block: 128 h's of one k. 8 warps load 64ch x 128h coalesced and transpose
// into smem via float4 STS (conflict-free). Then 128 threads each issue one
// 256B bulk-reduce into scratch[idx*64] and drain their own bulk group.
__global__ __launch_bounds__(256) void col2octree_scatter_tma(
    const float* __restrict__ data_in,   // [C, K, N]
    const int*   __restrict__ oct_t,     // [K, N]
    float*       __restrict__ scratch,   // [N, C]
    int K, int N)
{
    __shared__ __align__(16) float tile[TILE_H * SSTR];

    const int k    = blockIdx.y;
    const int h0   = blockIdx.x * TILE_H;
    const int t    = threadIdx.x;        // 256 threads
    const int lane = t & 31;
    const int w    = t >> 5;             // 8 warps

    // warps 0-3 cover h 0..127 for channel-quads 0..7; warps 4-7 for quads 8..15
    const int h_local = (w & 3) * 32 + lane;
    const int qbase   = (w >> 2) * 8;
    const int h       = h0 + h_local;

    const float* src = data_in + (size_t)k * N + h;
    const size_t cs  = (size_t)K * N;    // channel stride

    if (h < N) {
        #pragma unroll
        for (int i = 0; i < 8; ++i) {
            const int c = (qbase + i) * 4;
            float4 v;
            v.x = __ldcs(src + (size_t)(c + 0) * cs);
            v.y = __ldcs(src + (size_t)(c + 1) * cs);
            v.z = __ldcs(src + (size_t)(c + 2) * cs);
            v.w = __ldcs(src + (size_t)(c + 3) * cs);
            *reinterpret_cast<float4*>(&tile[h_local * SSTR + c]) = v;
        }
    }
    __syncthreads();

    // Per-thread TMA bulk-reduce: thread t (< 128) owns h0 + t.
    if (t < TILE_H && (h0 + t) < N) {
        const int idx = __ldg(&oct_t[(size_t)k * N + h0 + t]);
        if (idx >= 0) {
            uint32_t s = smem_u32(&tile[t * SSTR]);
            float* d = scratch + (size_t)idx * CH;
            asm volatile(
                "cp.reduce.async.bulk.global.shared::cta.bulk_group.add.f32 "
                "[%0], [%1], %2;"
                :: "l"(d), "r"(s), "r"((uint32_t)(CH * 4))
                : "memory");
        }
    }
    // Each thread drains its own bulk group (empty groups complete instantly).
    asm volatile("cp.async.bulk.commit_group;" ::: "memory");
    asm volatile("cp.async.bulk.wait_group 0;" ::: "memory");
}

// Fallback scalar-v4 scatter (used only if C != 64)
__global__ void col2octree_scatter_v4(
    const float* __restrict__ data_in, const int* __restrict__ oct_t,
    float* __restrict__ scratch, int C, int K, int N)
{
    const int h = blockIdx.x * blockDim.x + threadIdx.x;
    const int k = blockIdx.y;
    if (h >= N) return;
    const int idx = __ldg(&oct_t[(size_t)k * N + h]);
    if (idx < 0) return;
    const float* src = data_in + (size_t)k * N + h;
    const size_t cs = (size_t)K * N;
    float* dst = scratch + (size_t)idx * C;
    for (int c = 0; c + 4 <= C; c += 4) {
        float a = __ldcs(src + (size_t)(c + 0) * cs);
        float b = __ldcs(src + (size_t)(c + 1) * cs);
        float d = __ldcs(src + (size_t)(c + 2) * cs);
        float e = __ldcs(src + (size_t)(c + 3) * cs);
        asm volatile("red.global.add.v4.f32 [%0], {%1, %2, %3, %4};"
                     :: "l"(dst + c), "f"(a), "f"(b), "f"(d), "f"(e) : "memory");
    }
}

// [N, C] -> [C, N] transpose, 32x32 tiles via shared memory.
__global__ void transpose_nc_to_cn(
    const float* __restrict__ scratch, float* __restrict__ out, int C, int N)
{
    __shared__ float tile[32][33];
    const int n0 = blockIdx.x * 32;
    const int c0 = blockIdx.y * 32;
    const int tx = threadIdx.x;
    const int ty = threadIdx.y;

    #pragma unroll
    for (int i = ty; i < 32; i += 8) {
        int n = n0 + i;
        int c = c0 + tx;
        tile[i][tx] = (n < N && c < C) ? scratch[(size_t)n * C + c] : 0.f;
    }
    __syncthreads();
    #pragma unroll
    for (int i = ty; i < 32; i += 8) {
        int c = c0 + i;
        int n = n0 + tx;
        if (n < N && c < C) out[(size_t)c * N + n] = tile[tx][i];
    }
}

extern "C" void kernel_launch(void* const* d_in, const int* in_sizes, int n_in,
                              void* d_out, int out_size) {
    const float* data_in = (const float*)d_in[0];
    const int*   octree  = (const int*)d_in[1];
    float*       out     = (float*)d_out;

    const long long in0 = in_sizes[0];          // C*K*N
    const long long in1 = in_sizes[1];          // N*K
    const int C = (int)(in0 / in1);             // 64
    const int K = (int)(in0 / out_size);        // 27
    const int N = (int)(out_size / C);          // 200000

    float* scratch_ptr = nullptr;
    int*   oct_t_ptr   = nullptr;
    cudaGetSymbolAddress((void**)&scratch_ptr, g_scratch);
    cudaGetSymbolAddress((void**)&oct_t_ptr, g_octree_t);

    // 1) zero the [N, C] scratch (stream-ordered memset, graph-capturable)
    cudaMemsetAsync(scratch_ptr, 0, (size_t)N * C * sizeof(float));

    // 2) transpose octree [N, K] -> [K, N]
    transpose_octree<<<(N + 31) / 32, 256>>>(octree, oct_t_ptr, K, N);

    // 3) scatter-add
    if (C == CH) {
        dim3 blocks((N + TILE_H - 1) / TILE_H, K, 1);
        col2octree_scatter_tma<<<blocks, 256>>>(data_in, oct_t_ptr, scratch_ptr, K, N);
    } else {
        dim3 blocks((N + 255) / 256, K, 1);
        col2octree_scatter_v4<<<blocks, 256>>>(data_in, oct_t_ptr, scratch_ptr, C, K, N);
    }

    // 4) transpose [N, C] -> [C, N]
    {
        dim3 threads(32, 8, 1);
        dim3 blocks((N + 31) / 32, (C + 31) / 32, 1);
        transpose_nc_to_cn<<<blocks, threads>>>(scratch_ptr, out, C, N);
    }
}